// round 3
// baseline (speedup 1.0000x reference)
#include <cuda_runtime.h>
#include <cuda_bf16.h>

// Hawkes pairwise sum:  out[b,i] = sum_{j<i} ab[r_i,t_j] * exp(-b[r_i,t_j]*(T_i-T_j))
// Reformulated per pair as exp2(u*T_i + v) with
//   u = -beta*log2(e)             (per (t_j, r))
//   v = log2(alpha*beta) - u*T_j  (per (j, r), precomputed slab in smem)
// so the inner loop is: 2x LDS (conflict-free) + FFMA + MUFU.EX2 + FADD.
// B=8, L=2048, D=32. Times sorted -> exponent <= 0; reference's clip(-20,0)
// floor terms are <= 2e-9*ab each (dropped; validated rel_err ~1e-7).

constexpr int B = 8;
constexpr int L = 2048;
constexpr int D = 32;

constexpr int TI   = 256;                  // i-tile
constexpr int TJ   = 128;                  // j-half-tile (slab granularity)
constexpr int NT   = L / TI;               // 8
constexpr int NTRI = NT * (NT + 1) / 2;    // 36 triangular tiles / batch

constexpr float LOG2E = 1.4426950408889634f;

// Prebuilt tables, transposed to [trigger][receiver]:
__device__ float g_nb[D * D];   // -beta*log2(e)
__device__ float g_lg[D * D];   // log2(alpha*beta)

__device__ __forceinline__ float ex2f(float x) {
    float y;
    asm("ex2.approx.ftz.f32 %0, %1;" : "=f"(y) : "f"(x));
    return y;
}

__device__ __forceinline__ float softplusf(float x) {
    return fmaxf(x, 0.0f) + log1pf(expf(-fabsf(x)));
}

// Prep: zero the output AND build the (nb, lg) tables (block 0).
__global__ void prep_kernel(const float* __restrict__ log_alpha,
                            const float* __restrict__ log_beta,
                            float* __restrict__ out) {
    int i = blockIdx.x * blockDim.x + threadIdx.x;
    if (i < B * L) out[i] = 0.0f;
    if (blockIdx.x == 0) {
        for (int e = threadIdx.x; e < D * D; e += blockDim.x) {
            int r = e >> 5;          // receiver
            int t = e & (D - 1);     // trigger
            float a  = softplusf(log_alpha[e]);
            float bt = softplusf(log_beta[e]);
            g_nb[t * D + r] = -bt * LOG2E;
            g_lg[t * D + r] = __log2f(a * bt);
        }
    }
}

__global__ __launch_bounds__(TI)
void hawkes_kernel(const float* __restrict__ time_points,
                   const int*   __restrict__ event_types,
                   float*       __restrict__ out) {
    __shared__ float  s_nb[D * D];     // 4 KB
    __shared__ float  s_lg[D * D];     // 4 KB
    __shared__ float2 s_j[TI];         // 2 KB  {T_j, int_bits(t_j*32)}
    __shared__ float  s_u[TJ * D];     // 16 KB  slab: u[jj][r]
    __shared__ float  s_v[TJ * D];     // 16 KB  slab: v[jj][r]

    const int tid  = threadIdx.x;
    const int lane = tid & 31;
    const int wrp  = tid >> 5;
    const int blk  = blockIdx.x;
    const int b    = blk / NTRI;
    const int k    = blk % NTRI;

    // table copy (2 x 256 float4)
    {
        const float4* gn = reinterpret_cast<const float4*>(g_nb);
        const float4* gl = reinterpret_cast<const float4*>(g_lg);
        reinterpret_cast<float4*>(s_nb)[tid] = gn[tid];
        reinterpret_cast<float4*>(s_lg)[tid] = gl[tid];
    }

    // triangular decode: k -> (ti_, tj_) with tj_ <= ti_
    int ti_ = (int)((sqrtf(8.0f * (float)k + 1.0f) - 1.0f) * 0.5f);
    while ((ti_ + 1) * (ti_ + 2) / 2 <= k) ti_++;
    while (ti_ * (ti_ + 1) / 2 > k) ti_--;
    const int tj_ = k - ti_ * (ti_ + 1) / 2;
    const bool diag = (ti_ == tj_);

    // j-tile raw data
    {
        const int jg = b * L + tj_ * TI + tid;
        float tjv = time_points[jg];
        int   ctj = event_types[jg];
        ctj = ctj < 0 ? 0 : ctj;
        s_j[tid] = make_float2(tjv, __int_as_float(ctj << 5));
    }

    const int ig = b * L + ti_ * TI + tid;
    const float myt = time_points[ig];
    int r = event_types[ig];
    r = r < 0 ? 0 : r;

    const float* pu = s_u + r;
    const float* pv = s_v + r;

    float a8[8];
    #pragma unroll
    for (int c = 0; c < 8; ++c) a8[c] = 0.0f;

    __syncthreads();

    #pragma unroll 1
    for (int h = 0; h < 2; ++h) {
        // --- build slab for j in [h*TJ, h*TJ+TJ) ---
        // warp w, lane l handles (jj = w + 8k, r = l): conflict-free LDS/STS.
        #pragma unroll
        for (int kk = 0; kk < TJ / 8; ++kk) {
            int jj = wrp + 8 * kk;
            float2 p = s_j[h * TJ + jj];            // broadcast
            int tb = __float_as_int(p.y);
            float u  = s_nb[tb + lane];
            float lg = s_lg[tb + lane];
            s_u[jj * D + lane] = u;
            s_v[jj * D + lane] = fmaf(-u, p.x, lg);
        }
        __syncthreads();

        // --- inner loop over this half-tile ---
        if (!diag) {
            #pragma unroll 1
            for (int jj = 0; jj < TJ; jj += 8) {
                #pragma unroll
                for (int c = 0; c < 8; ++c) {
                    float u = pu[(jj + c) * D];
                    float v = pv[(jj + c) * D];
                    a8[c] += ex2f(fmaf(u, myt, v));
                }
            }
        } else {
            int lim = tid - h * TJ;
            lim = lim < 0 ? 0 : (lim > TJ ? TJ : lim);
            int l8 = lim & ~7;
            #pragma unroll 1
            for (int jj = 0; jj < l8; jj += 8) {
                #pragma unroll
                for (int c = 0; c < 8; ++c) {
                    float u = pu[(jj + c) * D];
                    float v = pv[(jj + c) * D];
                    a8[c] += ex2f(fmaf(u, myt, v));
                }
            }
            #pragma unroll 1
            for (int jj = l8; jj < lim; ++jj) {
                float u = pu[jj * D];
                float v = pv[jj * D];
                a8[0] += ex2f(fmaf(u, myt, v));
            }
        }
        __syncthreads();   // protect slab before next half rebuild
    }

    float acc = ((a8[0] + a8[1]) + (a8[2] + a8[3])) +
                ((a8[4] + a8[5]) + (a8[6] + a8[7]));
    atomicAdd(&out[ig], acc);
}

extern "C" void kernel_launch(void* const* d_in, const int* in_sizes, int n_in,
                              void* d_out, int out_size) {
    const float* time_points = (const float*)d_in[0];
    const int*   event_types = (const int*)d_in[1];
    const float* log_alpha   = (const float*)d_in[2];
    const float* log_beta    = (const float*)d_in[3];
    float* out = (float*)d_out;

    prep_kernel<<<(B * L + 255) / 256, 256>>>(log_alpha, log_beta, out);
    hawkes_kernel<<<B * NTRI, TI>>>(time_points, event_types, out);
}